// round 6
// baseline (speedup 1.0000x reference)
#include <cuda_runtime.h>
#include <cuda_bf16.h>
#include <cstdint>

// GMMVAE ELBO. Stage1 via mma.sync bf16 (swizzled operands), stage2 f32x2.
// 512 threads/CTA for occupancy; single-pass fixed-point finish.
typedef unsigned long long ull;

#define B_TOT 16384
#define XD 784
#define ZD 64
#define KK 64
#define ROWS 128
#define THREADS 512
#define NBLK (B_TOT / ROWS)   // 128
#define NTILES 98             // 784 / 8
#define HTILES 49             // per n-half
#define RSTR 65               // f32 row-array stride (stage 2)
#define LOG2PI 1.8378770664093453
#define FIXSCALE 262144.0     // 2^18

__device__ float g_s2T[ZD * KK];   // [z][k]
__device__ float g_na2T[ZD * KK];  // [z][k]
__device__ float g_cc2[KK];
__device__ float g_ck2[KK];
__device__ ull g_acc;
__device__ unsigned g_cnt;
__device__ __align__(16) __nv_bfloat16 g_Wt[XD * 64];  // [c][z] 128B rows, swizzled

// ---- smem byte offsets ----
#define OFF_RED   0        // 32 floats
#define OFF_BIAS  128      // 784 f32 -> 3264
#define OFF_ZBF   3328     // 128*128B = 16384 -> 19712 (bf16 swizzled)
#define OFF_ZR    19712    // [128][65] f32 = 33280 -> 52992
#define OFF_V1    52992    // -> 86272
#define OFF_WT    86272    // 784*128B = 100352 -> 186624
#define OFF_QM    186624   // 33280 -> 219904
// overlay in WT pool after stage1:
#define OFF_S2T   86272    // 16384
#define OFF_NA2T  102656   // 16384
#define OFF_COMP  119040   // 32768
#define OFF_KLZ   151808   // 32768 -> 184576
#define SMEM_BYTES 219904

__device__ __forceinline__ uint32_t smem_u32(const void* p) {
    uint32_t a;
    asm("{ .reg .u64 t; cvta.to.shared.u64 t, %1; cvt.u32.u64 %0, t; }" : "=r"(a) : "l"(p));
    return a;
}
__device__ __forceinline__ ull fma2o(ull a, ull b, ull c) {
    ull d;
    asm("fma.rn.f32x2 %0, %1, %2, %3;" : "=l"(d) : "l"(a), "l"(b), "l"(c));
    return d;
}
__device__ __forceinline__ ull dup2(float x) {
    ull r;
    asm("mov.b64 %0, {%1, %1};" : "=l"(r) : "f"(x));
    return r;
}
__device__ __forceinline__ void unpack2(ull v, float& lo, float& hi) {
    asm("mov.b64 {%0, %1}, %2;" : "=f"(lo), "=f"(hi) : "l"(v));
}
__device__ __forceinline__ void ldm_x4(uint32_t& r0, uint32_t& r1, uint32_t& r2,
                                       uint32_t& r3, uint32_t addr) {
    asm volatile("ldmatrix.sync.aligned.m8n8.x4.shared.b16 {%0,%1,%2,%3}, [%4];"
                 : "=r"(r0), "=r"(r1), "=r"(r2), "=r"(r3) : "r"(addr));
}
__device__ __forceinline__ void mma_bf16(float& c0, float& c1, float& c2, float& c3,
                                         uint32_t a0, uint32_t a1, uint32_t a2, uint32_t a3,
                                         uint32_t b0, uint32_t b1) {
    asm volatile("mma.sync.aligned.m16n8k16.row.col.f32.bf16.bf16.f32 "
                 "{%0,%1,%2,%3}, {%4,%5,%6,%7}, {%8,%9}, {%0,%1,%2,%3};"
                 : "+f"(c0), "+f"(c1), "+f"(c2), "+f"(c3)
                 : "r"(a0), "r"(a1), "r"(a2), "r"(a3), "r"(b0), "r"(b1));
}
// swizzled byte offset of f32-pair zp (0..31) within 128B row r
__device__ __forceinline__ uint32_t swz(int r, int zp) {
    return (uint32_t)(r * 128 + (((zp >> 2) ^ (r & 7)) << 4) + 4 * (zp & 3));
}

// ======================= prep kernel (grid 15) =======================
__global__ void prep_kernel(const float* __restrict__ W,
                            const float* __restrict__ pmu,
                            const float* __restrict__ pls) {
    const int b = blockIdx.x, tid = threadIdx.x;
    if (b < 14) {
        __shared__ float sc[64 * 57];
        const int c0 = b * 56;
        for (int i = tid; i < 64 * 56; i += 256) {
            const int z = i / 56, c = i - z * 56;
            sc[z * 57 + c] = W[z * XD + c0 + c];
        }
        __syncthreads();
        for (int i = tid; i < 56 * 32; i += 256) {
            const int c = i >> 5, zp = i & 31;
            __nv_bfloat162 bv = __floats2bfloat162_rn(sc[(2 * zp) * 57 + c],
                                                      sc[(2 * zp + 1) * 57 + c]);
            *(uint32_t*)((char*)g_Wt + swz(c0 + c, zp)) = *(uint32_t*)&bv;
        }
    } else {
        const int k = tid >> 2, q = tid & 3;
        float lsum = 0.f, c1 = 0.f;
#pragma unroll
        for (int i = 0; i < 16; i++) {
            const int z = 16 * q + i;
            float ls = pls[k * ZD + z];
            float mu = pmu[k * ZD + z];
            float s2i = expf(-2.f * ls);
            g_s2T[z * KK + k] = s2i;
            g_na2T[z * KK + k] = -2.f * mu * s2i;
            lsum += ls;
            c1 = fmaf(mu * mu, s2i, c1);
        }
#pragma unroll
        for (int o = 1; o < 4; o <<= 1) {
            lsum += __shfl_xor_sync(~0u, lsum, o);
            c1 += __shfl_xor_sync(~0u, c1, o);
        }
        if (q == 0) {
            g_cc2[k] = (float)(-(double)lsum - 32.0 * LOG2PI - 0.5 * (double)c1);
            g_ck2[k] = lsum + 0.5f * c1;
        }
        if (tid == 0) { g_acc = 0ull; g_cnt = 0u; }
    }
}

// ======================= main kernel =======================
extern __shared__ char smem[];

#define LDB(dst, t) do {                                                       \
    const uint32_t bt_ = (t) * 1024;                                           \
    ldm_x4((dst)[0], (dst)[1], (dst)[2], (dst)[3], baddr0 + bt_);              \
    ldm_x4((dst)[4], (dst)[5], (dst)[6], (dst)[7], baddr1 + bt_);              \
} while (0)

#define LDX(xa, xb, bb, t) do {                                                \
    bb = *(const float2*)(bP + 8 * (t));                                       \
    xa = *(const float2*)(pxA + 8 * (t));                                      \
    xb = *(const float2*)(pxB + 8 * (t));                                      \
} while (0)

#define TILE_BODY(bf, xa, xb, bb) do {                                         \
    float cA0 = 0.f, cA1 = 0.f, cA2 = 0.f, cA3 = 0.f;                          \
    float cB0 = 0.f, cB1 = 0.f, cB2 = 0.f, cB3 = 0.f;                          \
    mma_bf16(cA0, cA1, cA2, cA3, a[0], a[1], a[2], a[3], (bf)[0], (bf)[1]);    \
    mma_bf16(cB0, cB1, cB2, cB3, a[8], a[9], a[10], a[11], (bf)[4], (bf)[5]);  \
    mma_bf16(cA0, cA1, cA2, cA3, a[4], a[5], a[6], a[7], (bf)[2], (bf)[3]);    \
    mma_bf16(cB0, cB1, cB2, cB3, a[12], a[13], a[14], a[15], (bf)[6], (bf)[7]);\
    float d_;                                                                  \
    d_ = ((xa).x - (bb).x) - (cA0 + cB0); px = fmaf(d_, d_, px);               \
    d_ = ((xa).y - (bb).y) - (cA1 + cB1); px = fmaf(d_, d_, px);               \
    d_ = ((xb).x - (bb).x) - (cA2 + cB2); px = fmaf(d_, d_, px);               \
    d_ = ((xb).y - (bb).y) - (cA3 + cB3); px = fmaf(d_, d_, px);               \
} while (0)

__global__ __launch_bounds__(THREADS, 1)
void main_kernel(const float* __restrict__ x, const float* __restrict__ pi,
                 const float* __restrict__ qmu, const float* __restrict__ qls,
                 const float* __restrict__ eps, const float* __restrict__ bdec,
                 float* __restrict__ out) {
    const int tid = threadIdx.x;
    const int wid = tid >> 5, lane = tid & 31;
    const int rowbase = blockIdx.x * ROWS;
    const uint32_t sbase = smem_u32(smem);
    float* red = (float*)(smem + OFF_RED);
    float* biasS = (float*)(smem + OFF_BIAS);
    float* zR = (float*)(smem + OFF_ZR);
    float* v1S = (float*)(smem + OFF_V1);
    float* qmS = (float*)(smem + OFF_QM);

    // ---- load Wt into smem (raw swizzled image) ----
    {
        const uint4* src = (const uint4*)g_Wt;
        uint4* dst = (uint4*)(smem + OFF_WT);
        for (int i = tid; i < (XD * 128) / 16; i += THREADS) dst[i] = src[i];
    }
    for (int i = tid; i < XD; i += THREADS) biasS[i] = bdec[i];

    // ---- build z (bf16 swizzled) + zR/v1/qm f32 ----
    for (int i = tid; i < ROWS * 32; i += THREADS) {
        const int r = i >> 5, zp = i & 31;
        const int gi = (rowbase + r) * ZD + 2 * zp;
        float2 qm2 = *(const float2*)(qmu + gi);
        float2 ql2 = *(const float2*)(qls + gi);
        float2 ep2 = *(const float2*)(eps + gi);
        float qs0 = expf(ql2.x), qs1 = expf(ql2.y);
        float z0 = fmaf(qs0, ep2.x, qm2.x);
        float z1 = fmaf(qs1, ep2.y, qm2.y);
        __nv_bfloat162 bv = __floats2bfloat162_rn(z0, z1);
        *(uint32_t*)(smem + OFF_ZBF + swz(r, zp)) = *(uint32_t*)&bv;
        const int rb = r * RSTR + 2 * zp;
        zR[rb] = z0; zR[rb + 1] = z1;
        v1S[rb] = fmaf(qs0, qs0, qm2.x * qm2.x);
        v1S[rb + 1] = fmaf(qs1, qs1, qm2.y * qm2.y);
        qmS[rb] = qm2.x; qmS[rb + 1] = qm2.y;
    }
    __syncthreads();

    // ================= Stage 1: mean GEMM (mma.sync) + log_px ==============
    float px = 0.f;
    {
        const int g = lane >> 3, lr = lane & 7;
        const int mrow = 16 * (wid & 7);
        const int jbase = HTILES * (wid >> 3);
        uint32_t a[16];
        {
            const int ra = mrow + lr + 8 * (g & 1);
            const uint32_t abase = sbase + OFF_ZBF + ra * 128;
            const int gx = (g >> 1);
#pragma unroll
            for (int kt = 0; kt < 4; kt++)
                ldm_x4(a[4 * kt], a[4 * kt + 1], a[4 * kt + 2], a[4 * kt + 3],
                       abase + (uint32_t)(((gx + 2 * kt) ^ (ra & 7)) << 4));
        }
        const uint32_t baddr0 = sbase + OFF_WT + jbase * 1024 + lr * 128
                                + (uint32_t)((g ^ lr) << 4);
        const uint32_t baddr1 = sbase + OFF_WT + jbase * 1024 + lr * 128
                                + (uint32_t)(((g + 4) ^ lr) << 4);
        const float* pxA = x + (size_t)(rowbase + mrow + (lane >> 2)) * XD
                           + 2 * (lane & 3) + 8 * jbase;
        const float* pxB = pxA + 8 * XD;
        const float* bP = biasS + 2 * (lane & 3) + 8 * jbase;

        uint32_t b0[8], b1[8];
        float2 xaA, xbA, bbA, xaB, xbB, bbB;
        LDB(b0, 0);
        LDX(xaA, xbA, bbA, 0);
        for (int t = 1; t < HTILES; t += 2) {
            LDB(b1, t);
            LDX(xaB, xbB, bbB, t);
            TILE_BODY(b0, xaA, xbA, bbA);
            LDB(b0, t + 1);
            LDX(xaA, xbA, bbA, t + 1);
            TILE_BODY(b1, xaB, xbB, bbB);
        }
        TILE_BODY(b0, xaA, xbA, bbA);   // tile 48
    }
    __syncthreads();

    // ---- copy s2T/na2T into WT overlay ----
    float* s2T = (float*)(smem + OFF_S2T);
    float* na2T = (float*)(smem + OFF_NA2T);
    float* compS = (float*)(smem + OFF_COMP);
    float* klzS = (float*)(smem + OFF_KLZ);
    {
        const uint4* s1 = (const uint4*)g_s2T;
        const uint4* s2 = (const uint4*)g_na2T;
        uint4* d1 = (uint4*)s2T;
        uint4* d2 = (uint4*)na2T;
        for (int i = tid; i < (ZD * KK) / 4; i += THREADS) {
            d1[i] = s1[i];
            d2[i] = s2[i];
        }
    }
    __syncthreads();

    // ================= Stage 2a: quadratics, tile 2r x 8k per thread =========
    {
        const int tx = tid & 7, ty = tid >> 3;
        const int kb = 8 * tx, r0 = 2 * ty;
        ull accC[2][4], accK[2][4];
#pragma unroll
        for (int r = 0; r < 2; r++)
#pragma unroll
            for (int k = 0; k < 4; k++) { accC[r][k] = 0ull; accK[r][k] = 0ull; }

        const float* s2p = s2T + kb;
        const float* nap = na2T + kb;
#pragma unroll 4
        for (int z = 0; z < ZD; z++) {
            ulonglong2 sA = *(const ulonglong2*)(s2p + z * KK);
            ulonglong2 sB = *(const ulonglong2*)(s2p + z * KK + 4);
            ulonglong2 nA = *(const ulonglong2*)(nap + z * KK);
            ulonglong2 nB = *(const ulonglong2*)(nap + z * KK + 4);
#pragma unroll
            for (int r = 0; r < 2; r++) {
                const int rb = (r0 + r) * RSTR + z;
                ull zd = dup2(zR[rb]);
                ull vd = dup2(v1S[rb]);
                ull qd = dup2(qmS[rb]);
                ull t;
                t = fma2o(sA.x, zd, nA.x); accC[r][0] = fma2o(t, zd, accC[r][0]);
                t = fma2o(sA.y, zd, nA.y); accC[r][1] = fma2o(t, zd, accC[r][1]);
                t = fma2o(sB.x, zd, nB.x); accC[r][2] = fma2o(t, zd, accC[r][2]);
                t = fma2o(sB.y, zd, nB.y); accC[r][3] = fma2o(t, zd, accC[r][3]);
                accK[r][0] = fma2o(sA.x, vd, accK[r][0]);
                accK[r][0] = fma2o(nA.x, qd, accK[r][0]);
                accK[r][1] = fma2o(sA.y, vd, accK[r][1]);
                accK[r][1] = fma2o(nA.y, qd, accK[r][1]);
                accK[r][2] = fma2o(sB.x, vd, accK[r][2]);
                accK[r][2] = fma2o(nB.x, qd, accK[r][2]);
                accK[r][3] = fma2o(sB.y, vd, accK[r][3]);
                accK[r][3] = fma2o(nB.y, qd, accK[r][3]);
            }
        }
        float cc[8], ck[8];
        *(float4*)cc = *(const float4*)(g_cc2 + kb);
        *(float4*)(cc + 4) = *(const float4*)(g_cc2 + kb + 4);
        *(float4*)ck = *(const float4*)(g_ck2 + kb);
        *(float4*)(ck + 4) = *(const float4*)(g_ck2 + kb + 4);
#pragma unroll
        for (int r = 0; r < 2; r++) {
#pragma unroll
            for (int k = 0; k < 4; k++) {
                float lo, hi;
                unpack2(accC[r][k], lo, hi);
                *(float2*)(compS + (r0 + r) * KK + kb + 2 * k) =
                    make_float2(fmaf(-0.5f, lo, cc[2 * k]), fmaf(-0.5f, hi, cc[2 * k + 1]));
                unpack2(accK[r][k], lo, hi);
                *(float2*)(klzS + (r0 + r) * KK + kb + 2 * k) =
                    make_float2(fmaf(0.5f, lo, ck[2 * k]), fmaf(0.5f, hi, ck[2 * k + 1]));
            }
        }
    }
    __syncthreads();

    // ================= Stage 2b: softmax / KL (warp per row) =========
    float kl_acc = 0.f;
    for (int rr = 0; rr < 8; rr++) {
        const int r = wid + 16 * rr;
        const int grow = rowbase + r;
        float c0 = compS[r * KK + lane];
        float c1 = compS[r * KK + lane + 32];
        float k0 = klzS[r * KK + lane];
        float k1 = klzS[r * KK + lane + 32];
        float lp0 = logf(pi[grow * KK + lane]);
        float lp1 = logf(pi[grow * KK + lane + 32]);
        float q0 = qls[grow * ZD + lane];
        float q1 = qls[grow * ZD + lane + 32];

        float qsum = q0 + q1;
#pragma unroll
        for (int o = 16; o; o >>= 1) qsum += __shfl_xor_sync(~0u, qsum, o);
        float p0 = c0 + lp0, p1 = c1 + lp1;
        float m = fmaxf(p0, p1);
#pragma unroll
        for (int o = 16; o; o >>= 1) m = fmaxf(m, __shfl_xor_sync(~0u, m, o));
        float e0 = expf(p0 - m), e1 = expf(p1 - m);
        float es = e0 + e1;
#pragma unroll
        for (int o = 16; o; o >>= 1) es += __shfl_xor_sync(~0u, es, o);
        float lse = m + logf(es);
        float inv = 1.f / es;
        float pr0 = e0 * inv, pr1 = e1 * inv;
        float contrib = pr0 * (c0 - lse) + pr1 * (c1 - lse)
                      + pr0 * (k0 - qsum - 32.f) + pr1 * (k1 - qsum - 32.f);
#pragma unroll
        for (int o = 16; o; o >>= 1) contrib += __shfl_xor_sync(~0u, contrib, o);
        if (lane == 0) kl_acc += contrib;
    }

    // ---- deterministic block + grid reduction (fixed-point atomics) ----
    float pxw = px;
#pragma unroll
    for (int o = 16; o; o >>= 1) pxw += __shfl_xor_sync(~0u, pxw, o);
    if (lane == 0) { red[wid] = pxw; red[16 + wid] = kl_acc; }
    __syncthreads();
    if (tid == 0) {
        float sp = 0.f, sk = 0.f;
#pragma unroll
        for (int w = 0; w < 16; w++) { sp += red[w]; sk += red[16 + w]; }
        const double part = (double)(-0.5f * sp - sk);
        const long long q = llrint(part * FIXSCALE);
        atomicAdd(&g_acc, (ull)q);
        __threadfence();
        const unsigned t = atomicAdd(&g_cnt, 1u);
        if (t == NBLK - 1) {
            const long long tot = (long long)atomicAdd(&g_acc, 0ull);
            out[0] = (float)((double)tot / FIXSCALE / 16384.0
                             - 0.5 * LOG2PI * (double)XD);
            g_cnt = 0u;
            g_acc = 0ull;
        }
    }
}

extern "C" void kernel_launch(void* const* d_in, const int* in_sizes, int n_in,
                              void* d_out, int out_size) {
    (void)in_sizes; (void)n_in; (void)out_size;
    const float* x    = (const float*)d_in[0];
    const float* pi   = (const float*)d_in[1];
    const float* qmu  = (const float*)d_in[2];
    const float* qls  = (const float*)d_in[3];
    const float* eps  = (const float*)d_in[4];
    const float* pmu  = (const float*)d_in[5];
    const float* pls  = (const float*)d_in[6];
    const float* W    = (const float*)d_in[7];
    const float* bdec = (const float*)d_in[8];

    cudaFuncSetAttribute(main_kernel, cudaFuncAttributeMaxDynamicSharedMemorySize,
                         SMEM_BYTES);
    prep_kernel<<<15, 256>>>(W, pmu, pls);
    main_kernel<<<NBLK, THREADS, SMEM_BYTES>>>(x, pi, qmu, qls, eps, bdec,
                                               (float*)d_out);
}

// round 7
// speedup vs baseline: 1.0050x; 1.0050x over previous
#include <cuda_runtime.h>
#include <cuda_bf16.h>
#include <cstdint>

// GMMVAE ELBO. Stage1 via mma.sync bf16 (swizzled operands, deep x prefetch),
// stage2 f32x2 with z-pair loads. 512 threads/CTA, fixed-point finish.
typedef unsigned long long ull;

#define B_TOT 16384
#define XD 784
#define ZD 64
#define KK 64
#define ROWS 128
#define THREADS 512
#define NBLK (B_TOT / ROWS)   // 128
#define HTILES 49             // per n-half
#define RSTR 66               // f32 row-array stride (even -> float2 aligned)
#define LOG2PI 1.8378770664093453
#define FIXSCALE 262144.0     // 2^18

__device__ float g_s2T[ZD * KK];   // [z][k]
__device__ float g_na2T[ZD * KK];  // [z][k]
__device__ float g_cc2[KK];
__device__ float g_ck2[KK];
__device__ ull g_acc;
__device__ unsigned g_cnt;
__device__ __align__(16) __nv_bfloat16 g_Wt[XD * 64];  // [c][z] 128B rows, swizzled

// ---- smem byte offsets ----
#define OFF_RED   0        // 32 floats
#define OFF_BIAS  128      // 784 f32 -> 3264
#define OFF_ZBF   3328     // 128*128B = 16384 -> 19712 (bf16 swizzled)
#define OFF_ZR    19712    // [128][66] f32 = 33792 -> 53504
#define OFF_V1    53504    // -> 87296
#define OFF_WT    87296    // 784*128B = 100352 -> 187648
#define OFF_QM    187648   // 33792 -> 221440
// overlay in WT pool after stage1:
#define OFF_S2T   87296    // 16384
#define OFF_NA2T  103680   // 16384
#define OFF_COMP  120064   // 32768
#define OFF_KLZ   152832   // 32768 -> 185600
#define SMEM_BYTES 221440

__device__ __forceinline__ uint32_t smem_u32(const void* p) {
    uint32_t a;
    asm("{ .reg .u64 t; cvta.to.shared.u64 t, %1; cvt.u32.u64 %0, t; }" : "=r"(a) : "l"(p));
    return a;
}
__device__ __forceinline__ ull fma2o(ull a, ull b, ull c) {
    ull d;
    asm("fma.rn.f32x2 %0, %1, %2, %3;" : "=l"(d) : "l"(a), "l"(b), "l"(c));
    return d;
}
__device__ __forceinline__ ull dup2(float x) {
    ull r;
    asm("mov.b64 %0, {%1, %1};" : "=l"(r) : "f"(x));
    return r;
}
__device__ __forceinline__ void unpack2(ull v, float& lo, float& hi) {
    asm("mov.b64 {%0, %1}, %2;" : "=f"(lo), "=f"(hi) : "l"(v));
}
__device__ __forceinline__ void ldm_x4(uint32_t& r0, uint32_t& r1, uint32_t& r2,
                                       uint32_t& r3, uint32_t addr) {
    asm volatile("ldmatrix.sync.aligned.m8n8.x4.shared.b16 {%0,%1,%2,%3}, [%4];"
                 : "=r"(r0), "=r"(r1), "=r"(r2), "=r"(r3) : "r"(addr));
}
__device__ __forceinline__ void mma_bf16(float& c0, float& c1, float& c2, float& c3,
                                         uint32_t a0, uint32_t a1, uint32_t a2, uint32_t a3,
                                         uint32_t b0, uint32_t b1) {
    asm volatile("mma.sync.aligned.m16n8k16.row.col.f32.bf16.bf16.f32 "
                 "{%0,%1,%2,%3}, {%4,%5,%6,%7}, {%8,%9}, {%0,%1,%2,%3};"
                 : "+f"(c0), "+f"(c1), "+f"(c2), "+f"(c3)
                 : "r"(a0), "r"(a1), "r"(a2), "r"(a3), "r"(b0), "r"(b1));
}
// swizzled byte offset of f32-pair zp (0..31) within 128B row r
__device__ __forceinline__ uint32_t swz(int r, int zp) {
    return (uint32_t)(r * 128 + (((zp >> 2) ^ (r & 7)) << 4) + 4 * (zp & 3));
}

// ======================= prep kernel (grid 15) =======================
__global__ void prep_kernel(const float* __restrict__ W,
                            const float* __restrict__ pmu,
                            const float* __restrict__ pls) {
    const int b = blockIdx.x, tid = threadIdx.x;
    if (b < 14) {
        __shared__ float sc[64 * 57];
        const int c0 = b * 56;
        for (int i = tid; i < 64 * 56; i += 256) {
            const int z = i / 56, c = i - z * 56;
            sc[z * 57 + c] = W[z * XD + c0 + c];
        }
        __syncthreads();
        for (int i = tid; i < 56 * 32; i += 256) {
            const int c = i >> 5, zp = i & 31;
            __nv_bfloat162 bv = __floats2bfloat162_rn(sc[(2 * zp) * 57 + c],
                                                      sc[(2 * zp + 1) * 57 + c]);
            *(uint32_t*)((char*)g_Wt + swz(c0 + c, zp)) = *(uint32_t*)&bv;
        }
    } else {
        const int k = tid >> 2, q = tid & 3;
        float lsum = 0.f, c1 = 0.f;
#pragma unroll
        for (int i = 0; i < 16; i++) {
            const int z = 16 * q + i;
            float ls = pls[k * ZD + z];
            float mu = pmu[k * ZD + z];
            float s2i = expf(-2.f * ls);
            g_s2T[z * KK + k] = s2i;
            g_na2T[z * KK + k] = -2.f * mu * s2i;
            lsum += ls;
            c1 = fmaf(mu * mu, s2i, c1);
        }
#pragma unroll
        for (int o = 1; o < 4; o <<= 1) {
            lsum += __shfl_xor_sync(~0u, lsum, o);
            c1 += __shfl_xor_sync(~0u, c1, o);
        }
        if (q == 0) {
            g_cc2[k] = (float)(-(double)lsum - 32.0 * LOG2PI - 0.5 * (double)c1);
            g_ck2[k] = lsum + 0.5f * c1;
        }
        if (tid == 0) { g_acc = 0ull; g_cnt = 0u; }
    }
}

// ======================= main kernel =======================
extern __shared__ char smem[];

#define LDB(dst, t) do {                                                       \
    const uint32_t bt_ = (t) * 1024;                                           \
    ldm_x4((dst)[0], (dst)[1], (dst)[2], (dst)[3], baddr0 + bt_);              \
    ldm_x4((dst)[4], (dst)[5], (dst)[6], (dst)[7], baddr1 + bt_);              \
} while (0)

#define TILE_BODY(bf, xa, xb, bb) do {                                         \
    float cA0 = 0.f, cA1 = 0.f, cA2 = 0.f, cA3 = 0.f;                          \
    float cB0 = 0.f, cB1 = 0.f, cB2 = 0.f, cB3 = 0.f;                          \
    mma_bf16(cA0, cA1, cA2, cA3, a[0], a[1], a[2], a[3], (bf)[0], (bf)[1]);    \
    mma_bf16(cB0, cB1, cB2, cB3, a[8], a[9], a[10], a[11], (bf)[4], (bf)[5]);  \
    mma_bf16(cA0, cA1, cA2, cA3, a[4], a[5], a[6], a[7], (bf)[2], (bf)[3]);    \
    mma_bf16(cB0, cB1, cB2, cB3, a[12], a[13], a[14], a[15], (bf)[6], (bf)[7]);\
    float d_;                                                                  \
    d_ = ((xa).x - (bb).x) - (cA0 + cB0); px = fmaf(d_, d_, px);               \
    d_ = ((xa).y - (bb).y) - (cA1 + cB1); px = fmaf(d_, d_, px);               \
    d_ = ((xb).x - (bb).x) - (cA2 + cB2); px = fmaf(d_, d_, px);               \
    d_ = ((xb).y - (bb).y) - (cA3 + cB3); px = fmaf(d_, d_, px);               \
} while (0)

__global__ __launch_bounds__(THREADS, 1)
void main_kernel(const float* __restrict__ x, const float* __restrict__ pi,
                 const float* __restrict__ qmu, const float* __restrict__ qls,
                 const float* __restrict__ eps, const float* __restrict__ bdec,
                 float* __restrict__ out) {
    const int tid = threadIdx.x;
    const int wid = tid >> 5, lane = tid & 31;
    const int rowbase = blockIdx.x * ROWS;
    const uint32_t sbase = smem_u32(smem);
    float* red = (float*)(smem + OFF_RED);
    float* biasS = (float*)(smem + OFF_BIAS);
    float* zR = (float*)(smem + OFF_ZR);
    float* v1S = (float*)(smem + OFF_V1);
    float* qmS = (float*)(smem + OFF_QM);

    // ---- load Wt into smem (raw swizzled image) ----
    {
        const uint4* src = (const uint4*)g_Wt;
        uint4* dst = (uint4*)(smem + OFF_WT);
        for (int i = tid; i < (XD * 128) / 16; i += THREADS) dst[i] = src[i];
    }
    for (int i = tid; i < XD; i += THREADS) biasS[i] = bdec[i];

    // ---- build z (bf16 swizzled) + zR/v1/qm f32 ----
    for (int i = tid; i < ROWS * 32; i += THREADS) {
        const int r = i >> 5, zp = i & 31;
        const int gi = (rowbase + r) * ZD + 2 * zp;
        float2 qm2 = *(const float2*)(qmu + gi);
        float2 ql2 = *(const float2*)(qls + gi);
        float2 ep2 = *(const float2*)(eps + gi);
        float qs0 = expf(ql2.x), qs1 = expf(ql2.y);
        float z0 = fmaf(qs0, ep2.x, qm2.x);
        float z1 = fmaf(qs1, ep2.y, qm2.y);
        __nv_bfloat162 bv = __floats2bfloat162_rn(z0, z1);
        *(uint32_t*)(smem + OFF_ZBF + swz(r, zp)) = *(uint32_t*)&bv;
        const int rb = r * RSTR + 2 * zp;
        *(float2*)(zR + rb) = make_float2(z0, z1);
        *(float2*)(v1S + rb) = make_float2(fmaf(qs0, qs0, qm2.x * qm2.x),
                                           fmaf(qs1, qs1, qm2.y * qm2.y));
        *(float2*)(qmS + rb) = qm2;
    }
    __syncthreads();

    // ================= Stage 1: mean GEMM (mma.sync) + log_px ==============
    float px = 0.f;
    {
        const int g = lane >> 3, lr = lane & 7;
        const int mrow = 16 * (wid & 7);
        const int jbase = HTILES * (wid >> 3);
        uint32_t a[16];
        {
            const int ra = mrow + lr + 8 * (g & 1);
            const uint32_t abase = sbase + OFF_ZBF + ra * 128;
            const int gx = (g >> 1);
#pragma unroll
            for (int kt = 0; kt < 4; kt++)
                ldm_x4(a[4 * kt], a[4 * kt + 1], a[4 * kt + 2], a[4 * kt + 3],
                       abase + (uint32_t)(((gx + 2 * kt) ^ (ra & 7)) << 4));
        }
        const uint32_t baddr0 = sbase + OFF_WT + jbase * 1024 + lr * 128
                                + (uint32_t)((g ^ lr) << 4);
        const uint32_t baddr1 = sbase + OFF_WT + jbase * 1024 + lr * 128
                                + (uint32_t)(((g + 4) ^ lr) << 4);
        const float* pxA = x + (size_t)(rowbase + mrow + (lane >> 2)) * XD
                           + 2 * (lane & 3) + 8 * jbase;
        const float* pxB = pxA + 8 * XD;
        const float* bP = biasS + 2 * (lane & 3) + 8 * jbase;

        uint32_t b[2][8];
        float2 XA[2][4], XB[2][4];

        // deep prefetch: tail tile 48 first (consumed last), then group 0
        float2 xAt = *(const float2*)(pxA + 8 * 48);
        float2 xBt = *(const float2*)(pxB + 8 * 48);
#pragma unroll
        for (int t = 0; t < 4; t++) {
            XA[0][t] = *(const float2*)(pxA + 8 * t);
            XB[0][t] = *(const float2*)(pxB + 8 * t);
        }
        LDB(b[0], 0);

#pragma unroll 2
        for (int gg = 0; gg < 12; gg++) {
            const int nb = (gg + 1) & 1;
            if (gg < 11) {
#pragma unroll
                for (int t = 0; t < 4; t++) {
                    XA[nb][t] = *(const float2*)(pxA + 8 * (4 * gg + 4 + t));
                    XB[nb][t] = *(const float2*)(pxB + 8 * (4 * gg + 4 + t));
                }
            }
#pragma unroll
            for (int t = 0; t < 4; t++) {
                const int j = 4 * gg + t;
                LDB(b[(j + 1) & 1], j + 1);
                float2 bb = *(const float2*)(bP + 8 * j);
                TILE_BODY(b[j & 1], XA[gg & 1][t], XB[gg & 1][t], bb);
            }
        }
        float2 bbt = *(const float2*)(bP + 8 * 48);
        TILE_BODY(b[0], xAt, xBt, bbt);
    }
    __syncthreads();

    // ---- copy s2T/na2T into WT overlay ----
    float* s2T = (float*)(smem + OFF_S2T);
    float* na2T = (float*)(smem + OFF_NA2T);
    float* compS = (float*)(smem + OFF_COMP);
    float* klzS = (float*)(smem + OFF_KLZ);
    {
        const uint4* s1 = (const uint4*)g_s2T;
        const uint4* s2 = (const uint4*)g_na2T;
        uint4* d1 = (uint4*)s2T;
        uint4* d2 = (uint4*)na2T;
        for (int i = tid; i < (ZD * KK) / 4; i += THREADS) {
            d1[i] = s1[i];
            d2[i] = s2[i];
        }
    }
    __syncthreads();

    // ================= Stage 2a: quadratics, tile 2r x 8k, z-pairs ==========
    {
        const int tx = tid & 7, ty = tid >> 3;
        const int kb = 8 * tx, r0 = 2 * ty;
        ull accC[2][4], accK[2][4];
#pragma unroll
        for (int r = 0; r < 2; r++)
#pragma unroll
            for (int k = 0; k < 4; k++) { accC[r][k] = 0ull; accK[r][k] = 0ull; }

        const float* s2p = s2T + kb;
        const float* nap = na2T + kb;
        const int rb0 = r0 * RSTR, rb1 = rb0 + RSTR;
#pragma unroll 2
        for (int z = 0; z < ZD; z += 2) {
            ulonglong2 sA0 = *(const ulonglong2*)(s2p + z * KK);
            ulonglong2 sB0 = *(const ulonglong2*)(s2p + z * KK + 4);
            ulonglong2 nA0 = *(const ulonglong2*)(nap + z * KK);
            ulonglong2 nB0 = *(const ulonglong2*)(nap + z * KK + 4);
            ulonglong2 sA1 = *(const ulonglong2*)(s2p + (z + 1) * KK);
            ulonglong2 sB1 = *(const ulonglong2*)(s2p + (z + 1) * KK + 4);
            ulonglong2 nA1 = *(const ulonglong2*)(nap + (z + 1) * KK);
            ulonglong2 nB1 = *(const ulonglong2*)(nap + (z + 1) * KK + 4);
#pragma unroll
            for (int r = 0; r < 2; r++) {
                const int rb = (r ? rb1 : rb0) + z;
                float2 zf = *(const float2*)(zR + rb);
                float2 vf = *(const float2*)(v1S + rb);
                float2 qf = *(const float2*)(qmS + rb);
                ull zd = dup2(zf.x), vd = dup2(vf.x), qd = dup2(qf.x);
                ull t;
                t = fma2o(sA0.x, zd, nA0.x); accC[r][0] = fma2o(t, zd, accC[r][0]);
                t = fma2o(sA0.y, zd, nA0.y); accC[r][1] = fma2o(t, zd, accC[r][1]);
                t = fma2o(sB0.x, zd, nB0.x); accC[r][2] = fma2o(t, zd, accC[r][2]);
                t = fma2o(sB0.y, zd, nB0.y); accC[r][3] = fma2o(t, zd, accC[r][3]);
                accK[r][0] = fma2o(sA0.x, vd, accK[r][0]);
                accK[r][0] = fma2o(nA0.x, qd, accK[r][0]);
                accK[r][1] = fma2o(sA0.y, vd, accK[r][1]);
                accK[r][1] = fma2o(nA0.y, qd, accK[r][1]);
                accK[r][2] = fma2o(sB0.x, vd, accK[r][2]);
                accK[r][2] = fma2o(nB0.x, qd, accK[r][2]);
                accK[r][3] = fma2o(sB0.y, vd, accK[r][3]);
                accK[r][3] = fma2o(nB0.y, qd, accK[r][3]);
                zd = dup2(zf.y); vd = dup2(vf.y); qd = dup2(qf.y);
                t = fma2o(sA1.x, zd, nA1.x); accC[r][0] = fma2o(t, zd, accC[r][0]);
                t = fma2o(sA1.y, zd, nA1.y); accC[r][1] = fma2o(t, zd, accC[r][1]);
                t = fma2o(sB1.x, zd, nB1.x); accC[r][2] = fma2o(t, zd, accC[r][2]);
                t = fma2o(sB1.y, zd, nB1.y); accC[r][3] = fma2o(t, zd, accC[r][3]);
                accK[r][0] = fma2o(sA1.x, vd, accK[r][0]);
                accK[r][0] = fma2o(nA1.x, qd, accK[r][0]);
                accK[r][1] = fma2o(sA1.y, vd, accK[r][1]);
                accK[r][1] = fma2o(nA1.y, qd, accK[r][1]);
                accK[r][2] = fma2o(sB1.x, vd, accK[r][2]);
                accK[r][2] = fma2o(nB1.x, qd, accK[r][2]);
                accK[r][3] = fma2o(sB1.y, vd, accK[r][3]);
                accK[r][3] = fma2o(nB1.y, qd, accK[r][3]);
            }
        }
        float cc[8], ck[8];
        *(float4*)cc = *(const float4*)(g_cc2 + kb);
        *(float4*)(cc + 4) = *(const float4*)(g_cc2 + kb + 4);
        *(float4*)ck = *(const float4*)(g_ck2 + kb);
        *(float4*)(ck + 4) = *(const float4*)(g_ck2 + kb + 4);
#pragma unroll
        for (int r = 0; r < 2; r++) {
#pragma unroll
            for (int k = 0; k < 4; k++) {
                float lo, hi;
                unpack2(accC[r][k], lo, hi);
                *(float2*)(compS + (r0 + r) * KK + kb + 2 * k) =
                    make_float2(fmaf(-0.5f, lo, cc[2 * k]), fmaf(-0.5f, hi, cc[2 * k + 1]));
                unpack2(accK[r][k], lo, hi);
                *(float2*)(klzS + (r0 + r) * KK + kb + 2 * k) =
                    make_float2(fmaf(0.5f, lo, ck[2 * k]), fmaf(0.5f, hi, ck[2 * k + 1]));
            }
        }
    }
    __syncthreads();

    // ================= Stage 2b: softmax / KL (warp per row) =========
    float kl_acc = 0.f;
    for (int rr = 0; rr < 8; rr++) {
        const int r = wid + 16 * rr;
        const int grow = rowbase + r;
        float c0 = compS[r * KK + lane];
        float c1 = compS[r * KK + lane + 32];
        float k0 = klzS[r * KK + lane];
        float k1 = klzS[r * KK + lane + 32];
        float lp0 = logf(pi[grow * KK + lane]);
        float lp1 = logf(pi[grow * KK + lane + 32]);
        float q0 = qls[grow * ZD + lane];
        float q1 = qls[grow * ZD + lane + 32];

        float qsum = q0 + q1;
#pragma unroll
        for (int o = 16; o; o >>= 1) qsum += __shfl_xor_sync(~0u, qsum, o);
        float p0 = c0 + lp0, p1 = c1 + lp1;
        float m = fmaxf(p0, p1);
#pragma unroll
        for (int o = 16; o; o >>= 1) m = fmaxf(m, __shfl_xor_sync(~0u, m, o));
        float e0 = expf(p0 - m), e1 = expf(p1 - m);
        float es = e0 + e1;
#pragma unroll
        for (int o = 16; o; o >>= 1) es += __shfl_xor_sync(~0u, es, o);
        float lse = m + logf(es);
        float inv = 1.f / es;
        float pr0 = e0 * inv, pr1 = e1 * inv;
        float contrib = pr0 * (c0 - lse) + pr1 * (c1 - lse)
                      + pr0 * (k0 - qsum - 32.f) + pr1 * (k1 - qsum - 32.f);
#pragma unroll
        for (int o = 16; o; o >>= 1) contrib += __shfl_xor_sync(~0u, contrib, o);
        if (lane == 0) kl_acc += contrib;
    }

    // ---- deterministic block + grid reduction (fixed-point atomics) ----
    float pxw = px;
#pragma unroll
    for (int o = 16; o; o >>= 1) pxw += __shfl_xor_sync(~0u, pxw, o);
    if (lane == 0) { red[wid] = pxw; red[16 + wid] = kl_acc; }
    __syncthreads();
    if (tid == 0) {
        float sp = 0.f, sk = 0.f;
#pragma unroll
        for (int w = 0; w < 16; w++) { sp += red[w]; sk += red[16 + w]; }
        const double part = (double)(-0.5f * sp - sk);
        const long long q = llrint(part * FIXSCALE);
        atomicAdd(&g_acc, (ull)q);
        __threadfence();
        const unsigned t = atomicAdd(&g_cnt, 1u);
        if (t == NBLK - 1) {
            const long long tot = (long long)atomicAdd(&g_acc, 0ull);
            out[0] = (float)((double)tot / FIXSCALE / 16384.0
                             - 0.5 * LOG2PI * (double)XD);
            g_cnt = 0u;
            g_acc = 0ull;
        }
    }
}

extern "C" void kernel_launch(void* const* d_in, const int* in_sizes, int n_in,
                              void* d_out, int out_size) {
    (void)in_sizes; (void)n_in; (void)out_size;
    const float* x    = (const float*)d_in[0];
    const float* pi   = (const float*)d_in[1];
    const float* qmu  = (const float*)d_in[2];
    const float* qls  = (const float*)d_in[3];
    const float* eps  = (const float*)d_in[4];
    const float* pmu  = (const float*)d_in[5];
    const float* pls  = (const float*)d_in[6];
    const float* W    = (const float*)d_in[7];
    const float* bdec = (const float*)d_in[8];

    cudaFuncSetAttribute(main_kernel, cudaFuncAttributeMaxDynamicSharedMemorySize,
                         SMEM_BYTES);
    prep_kernel<<<15, 256>>>(W, pmu, pls);
    main_kernel<<<NBLK, THREADS, SMEM_BYTES>>>(x, pi, qmu, qls, eps, bdec,
                                               (float*)d_out);
}